// round 2
// baseline (speedup 1.0000x reference)
#include <cuda_runtime.h>
#include <cuda_bf16.h>
#include <mma.h>

using namespace nvcuda;

#define T_TOK   2048
#define IDIM_   1024
#define HIDDEN_ 4096
#define NEXP    8

#define BM 64
#define BN 64
#define BK 32

// ---- device scratch (allocation-free: static device globals) ----
__device__ int   g_count[NEXP];
__device__ int   g_offset[NEXP];
__device__ int   g_tok[NEXP][T_TOK];
__device__ float g_w[NEXP][T_TOK];
// h rows: compacted pairs, total exactly 2*T rows of HIDDEN floats = 64 MB
__device__ float g_h[(size_t)2 * T_TOK * HIDDEN_];

// ---------------------------------------------------------------
__global__ void zero_counts_kernel() {
    if (threadIdx.x < NEXP) g_count[threadIdx.x] = 0;
}

// one warp per token: router logits, top-2, softmax, slot assignment
__global__ void router_kernel(const float* __restrict__ xs,
                              const float* __restrict__ Wg) {
    int gwarp = (blockIdx.x * blockDim.x + threadIdx.x) >> 5;
    int lane  = threadIdx.x & 31;
    if (gwarp >= T_TOK) return;
    const float* x = xs + (size_t)gwarp * IDIM_;

    float acc[NEXP];
#pragma unroll
    for (int e = 0; e < NEXP; e++) acc[e] = 0.f;

    for (int k = lane; k < IDIM_; k += 32) {
        float xv = x[k];
#pragma unroll
        for (int e = 0; e < NEXP; e++)
            acc[e] += xv * Wg[e * IDIM_ + k];
    }
#pragma unroll
    for (int e = 0; e < NEXP; e++) {
#pragma unroll
        for (int off = 16; off; off >>= 1)
            acc[e] += __shfl_xor_sync(0xffffffffu, acc[e], off);
    }
    if (lane == 0) {
        // top-2 (strict > => lower index wins ties, matching top_k)
        int i0 = 0; float v0 = acc[0];
#pragma unroll
        for (int e = 1; e < NEXP; e++)
            if (acc[e] > v0) { v0 = acc[e]; i0 = e; }
        int i1 = -1; float v1 = -3.4e38f;
#pragma unroll
        for (int e = 0; e < NEXP; e++)
            if (e != i0 && acc[e] > v1) { v1 = acc[e]; i1 = e; }
        // softmax over [v0, v1] (v0 >= v1)
        float e1 = expf(v1 - v0);
        float s  = 1.0f + e1;
        float w0 = 1.0f / s;
        float w1 = e1 / s;
        int s0 = atomicAdd(&g_count[i0], 1);
        g_tok[i0][s0] = gwarp; g_w[i0][s0] = w0;
        int s1 = atomicAdd(&g_count[i1], 1);
        g_tok[i1][s1] = gwarp; g_w[i1][s1] = w1;
    }
}

__global__ void compute_offsets_kernel() {
    if (threadIdx.x == 0) {
        int off = 0;
#pragma unroll
        for (int e = 0; e < NEXP; e++) { g_offset[e] = off; off += g_count[e]; }
    }
}

// ---------------------------------------------------------------
// GEMM1: h[pair, HIDDEN] = relu( gather(xs) @ W1[e] + b1[e] )
// grid: x = HIDDEN/BN, y = T/BM (worst case), z = expert
__global__ __launch_bounds__(128)
void ffn1_kernel(const float* __restrict__ xs,
                 const float* __restrict__ W1,
                 const float* __restrict__ b1) {
    int e   = blockIdx.z;
    int cnt = g_count[e];
    int m0  = blockIdx.y * BM;
    if (m0 >= cnt) return;
    int n0  = blockIdx.x * BN;

    const float* B = W1 + (size_t)e * IDIM_ * HIDDEN_;
    float* hbase   = g_h + (size_t)g_offset[e] * HIDDEN_;

    __shared__ float As[BM][BK + 4];
    __shared__ float Bs[BK][BN + 4];
    __shared__ float Cs[BM][BN + 4];

    int tid  = threadIdx.x;
    int warp = tid >> 5;
    int wm   = (warp >> 1) * 32;
    int wn   = (warp & 1) * 32;

    wmma::fragment<wmma::accumulator, 16, 16, 8, float> c[2][2];
#pragma unroll
    for (int i = 0; i < 2; i++)
#pragma unroll
        for (int j = 0; j < 2; j++) wmma::fill_fragment(c[i][j], 0.0f);

    for (int k0 = 0; k0 < IDIM_; k0 += BK) {
        // A tile 64x32 (gather rows via token list)
#pragma unroll
        for (int i = 0; i < 16; i++) {
            int idx = tid + i * 128;
            int r = idx >> 5, cc = idx & 31;
            int m = m0 + r;
            float v = 0.f;
            if (m < cnt) v = xs[(size_t)g_tok[e][m] * IDIM_ + k0 + cc];
            As[r][cc] = v;
        }
        // B tile 32x64
#pragma unroll
        for (int i = 0; i < 16; i++) {
            int idx = tid + i * 128;
            int kr = idx >> 6, nc = idx & 63;
            Bs[kr][nc] = B[(size_t)(k0 + kr) * HIDDEN_ + n0 + nc];
        }
        __syncthreads();
#pragma unroll
        for (int kk = 0; kk < BK; kk += 8) {
            wmma::fragment<wmma::matrix_a, 16, 16, 8, wmma::precision::tf32, wmma::row_major> a[2];
            wmma::fragment<wmma::matrix_b, 16, 16, 8, wmma::precision::tf32, wmma::row_major> b[2];
#pragma unroll
            for (int i = 0; i < 2; i++) {
                wmma::load_matrix_sync(a[i], &As[wm + i * 16][kk], BK + 4);
#pragma unroll
                for (int t = 0; t < a[i].num_elements; t++)
                    a[i].x[t] = wmma::__float_to_tf32(a[i].x[t]);
            }
#pragma unroll
            for (int j = 0; j < 2; j++) {
                wmma::load_matrix_sync(b[j], &Bs[kk][wn + j * 16], BN + 4);
#pragma unroll
                for (int t = 0; t < b[j].num_elements; t++)
                    b[j].x[t] = wmma::__float_to_tf32(b[j].x[t]);
            }
#pragma unroll
            for (int i = 0; i < 2; i++)
#pragma unroll
                for (int j = 0; j < 2; j++)
                    wmma::mma_sync(c[i][j], a[i], b[j], c[i][j]);
        }
        __syncthreads();
    }

#pragma unroll
    for (int i = 0; i < 2; i++)
#pragma unroll
        for (int j = 0; j < 2; j++)
            wmma::store_matrix_sync(&Cs[wm + i * 16][wn + j * 16], c[i][j], BN + 4,
                                    wmma::mem_row_major);
    __syncthreads();

    const float* bias = b1 + (size_t)e * HIDDEN_;
#pragma unroll
    for (int i = 0; i < 32; i++) {
        int idx = tid + i * 128;
        int r = idx >> 6, cc = idx & 63;
        int m = m0 + r;
        if (m < cnt) {
            float v = Cs[r][cc] + bias[n0 + cc];
            v = v > 0.f ? v : 0.f;
            hbase[(size_t)m * HIDDEN_ + n0 + cc] = v;
        }
    }
}

// ---------------------------------------------------------------
// GEMM2: out[tok] += w * ( h @ W2[e] + b2[e] )
// grid: x = IDIM/BN, y = T/BM (worst case), z = expert
__global__ __launch_bounds__(128)
void ffn2_kernel(const float* __restrict__ W2,
                 const float* __restrict__ b2,
                 float* __restrict__ out) {
    int e   = blockIdx.z;
    int cnt = g_count[e];
    int m0  = blockIdx.y * BM;
    if (m0 >= cnt) return;
    int n0  = blockIdx.x * BN;

    const float* B = W2 + (size_t)e * HIDDEN_ * IDIM_;
    const float* hbase = g_h + (size_t)g_offset[e] * HIDDEN_;

    __shared__ float As[BM][BK + 4];
    __shared__ float Bs[BK][BN + 4];
    __shared__ float Cs[BM][BN + 4];

    int tid  = threadIdx.x;
    int warp = tid >> 5;
    int wm   = (warp >> 1) * 32;
    int wn   = (warp & 1) * 32;

    wmma::fragment<wmma::accumulator, 16, 16, 8, float> c[2][2];
#pragma unroll
    for (int i = 0; i < 2; i++)
#pragma unroll
        for (int j = 0; j < 2; j++) wmma::fill_fragment(c[i][j], 0.0f);

    for (int k0 = 0; k0 < HIDDEN_; k0 += BK) {
#pragma unroll
        for (int i = 0; i < 16; i++) {
            int idx = tid + i * 128;
            int r = idx >> 5, cc = idx & 31;
            int m = m0 + r;
            float v = 0.f;
            if (m < cnt) v = hbase[(size_t)m * HIDDEN_ + k0 + cc];
            As[r][cc] = v;
        }
#pragma unroll
        for (int i = 0; i < 16; i++) {
            int idx = tid + i * 128;
            int kr = idx >> 6, nc = idx & 63;
            Bs[kr][nc] = B[(size_t)(k0 + kr) * IDIM_ + n0 + nc];
        }
        __syncthreads();
#pragma unroll
        for (int kk = 0; kk < BK; kk += 8) {
            wmma::fragment<wmma::matrix_a, 16, 16, 8, wmma::precision::tf32, wmma::row_major> a[2];
            wmma::fragment<wmma::matrix_b, 16, 16, 8, wmma::precision::tf32, wmma::row_major> b[2];
#pragma unroll
            for (int i = 0; i < 2; i++) {
                wmma::load_matrix_sync(a[i], &As[wm + i * 16][kk], BK + 4);
#pragma unroll
                for (int t = 0; t < a[i].num_elements; t++)
                    a[i].x[t] = wmma::__float_to_tf32(a[i].x[t]);
            }
#pragma unroll
            for (int j = 0; j < 2; j++) {
                wmma::load_matrix_sync(b[j], &Bs[kk][wn + j * 16], BN + 4);
#pragma unroll
                for (int t = 0; t < b[j].num_elements; t++)
                    b[j].x[t] = wmma::__float_to_tf32(b[j].x[t]);
            }
#pragma unroll
            for (int i = 0; i < 2; i++)
#pragma unroll
                for (int j = 0; j < 2; j++)
                    wmma::mma_sync(c[i][j], a[i], b[j], c[i][j]);
        }
        __syncthreads();
    }

#pragma unroll
    for (int i = 0; i < 2; i++)
#pragma unroll
        for (int j = 0; j < 2; j++)
            wmma::store_matrix_sync(&Cs[wm + i * 16][wn + j * 16], c[i][j], BN + 4,
                                    wmma::mem_row_major);
    __syncthreads();

    const float* bias = b2 + (size_t)e * IDIM_;
#pragma unroll
    for (int i = 0; i < 32; i++) {
        int idx = tid + i * 128;
        int r = idx >> 6, cc = idx & 63;
        int m = m0 + r;
        if (m < cnt) {
            float v = Cs[r][cc] + bias[n0 + cc];
            float w = g_w[e][m];
            int tok = g_tok[e][m];
            // exactly 2 atomic adds per output element; 2-operand fp add is
            // commutative -> bitwise deterministic
            atomicAdd(&out[(size_t)tok * IDIM_ + n0 + cc], w * v);
        }
    }
}

// ---------------------------------------------------------------
extern "C" void kernel_launch(void* const* d_in, const int* in_sizes, int n_in,
                              void* d_out, int out_size) {
    const float* xs = (const float*)d_in[0];
    // d_in[1] = top_k (int32 scalar) -- fixed at 2 for this problem
    const float* Wg = (const float*)d_in[2];
    const float* W1 = (const float*)d_in[3];
    const float* b1 = (const float*)d_in[4];
    const float* W2 = (const float*)d_in[5];
    const float* b2 = (const float*)d_in[6];
    float* out = (float*)d_out;

    cudaMemsetAsync(out, 0, (size_t)T_TOK * IDIM_ * sizeof(float));
    zero_counts_kernel<<<1, 32>>>();
    router_kernel<<<(T_TOK * 32 + 1023) / 1024, 1024>>>(xs, Wg);
    compute_offsets_kernel<<<1, 32>>>();
    ffn1_kernel<<<dim3(HIDDEN_ / BN, T_TOK / BM, NEXP), 128>>>(xs, W1, b1);
    ffn2_kernel<<<dim3(IDIM_ / BN, T_TOK / BM, NEXP), 128>>>(W2, b2, out);
}

// round 4
// speedup vs baseline: 1.1217x; 1.1217x over previous
#include <cuda_runtime.h>
#include <cuda_bf16.h>
#include <mma.h>

using namespace nvcuda;

#define T_TOK   2048
#define IDIM_   1024
#define HIDDEN_ 4096
#define NEXP    8

#define BM 128
#define BN 64
#define BK 16
#define THREADS 256

#define AS_STRIDE (BK + 4)            /* 20 floats, 16B-aligned rows */
#define AS_TILE   (BM * AS_STRIDE)    /* 2560 */
#define BS_STRIDE (BN + 4)            /* 68 */
#define BS_TILE   (BK * BS_STRIDE)    /* 1088 */
#define C_STRIDE  (BN + 4)
#define SBUF_FLOATS (BM * C_STRIDE)   /* 8704 floats = 34.8KB >= 2*AS+2*BS = 7296 */

// ---- device scratch (allocation-free: static device globals) ----
__device__ int   g_count[NEXP];
__device__ int   g_offset[NEXP];
__device__ int   g_tok[NEXP][T_TOK];
__device__ float g_w[NEXP][T_TOK];
__device__ float g_h[(size_t)2 * T_TOK * HIDDEN_];   // compacted hidden rows

// ---------------------------------------------------------------
__global__ void zero_counts_kernel() {
    if (threadIdx.x < NEXP) g_count[threadIdx.x] = 0;
}

// one warp per token: router logits, top-2, softmax, slot assignment
__global__ void router_kernel(const float* __restrict__ xs,
                              const float* __restrict__ Wg) {
    int gwarp = (blockIdx.x * blockDim.x + threadIdx.x) >> 5;
    int lane  = threadIdx.x & 31;
    if (gwarp >= T_TOK) return;
    const float4* x = (const float4*)(xs + (size_t)gwarp * IDIM_);

    float acc[NEXP];
#pragma unroll
    for (int e = 0; e < NEXP; e++) acc[e] = 0.f;

    for (int k = lane; k < IDIM_ / 4; k += 32) {
        float4 xv = x[k];
#pragma unroll
        for (int e = 0; e < NEXP; e++) {
            const float4 wv = ((const float4*)(Wg + e * IDIM_))[k];
            acc[e] += xv.x * wv.x + xv.y * wv.y + xv.z * wv.z + xv.w * wv.w;
        }
    }
#pragma unroll
    for (int e = 0; e < NEXP; e++) {
#pragma unroll
        for (int off = 16; off; off >>= 1)
            acc[e] += __shfl_xor_sync(0xffffffffu, acc[e], off);
    }
    if (lane == 0) {
        int i0 = 0; float v0 = acc[0];
#pragma unroll
        for (int e = 1; e < NEXP; e++)
            if (acc[e] > v0) { v0 = acc[e]; i0 = e; }
        int i1 = -1; float v1 = -3.4e38f;
#pragma unroll
        for (int e = 0; e < NEXP; e++)
            if (e != i0 && acc[e] > v1) { v1 = acc[e]; i1 = e; }
        float e1 = expf(v1 - v0);
        float s  = 1.0f + e1;
        int s0 = atomicAdd(&g_count[i0], 1);
        g_tok[i0][s0] = gwarp; g_w[i0][s0] = 1.0f / s;
        int s1 = atomicAdd(&g_count[i1], 1);
        g_tok[i1][s1] = gwarp; g_w[i1][s1] = e1 / s;
    }
}

__global__ void compute_offsets_kernel() {
    if (threadIdx.x == 0) {
        int off = 0;
#pragma unroll
        for (int e = 0; e < NEXP; e++) { g_offset[e] = off; off += g_count[e]; }
    }
}

// ---------------------------------------------------------------
// Unified grouped GEMM.
// PHASE1: C = relu(gather(xs) @ W1[e] + b1[e]) -> g_h    (K=IDIM, N=HIDDEN)
// PHASE2: out[tok] += w * (g_h @ W2[e] + b2[e])          (K=HIDDEN, N=IDIM)
template <int KDIM, int N, bool PHASE1>
__global__ __launch_bounds__(THREADS)
void moe_gemm(const float* __restrict__ Aglob,   // xs (phase1) / unused (phase2)
              const float* __restrict__ Bglob,   // W1 / W2
              const float* __restrict__ biasg,   // b1 / b2
              float* __restrict__ outg) {        // unused / out
    int e   = blockIdx.z;
    int cnt = g_count[e];
    int m0  = blockIdx.y * BM;
    if (m0 >= cnt) return;
    int n0  = blockIdx.x * BN;

    __shared__ __align__(16) float sbuf[SBUF_FLOATS];
    float* As = sbuf;                   // [2][AS_TILE]
    float* Bs = sbuf + 2 * AS_TILE;     // [2][BS_TILE]

    const float* Bp = Bglob + (size_t)e * KDIM * N + n0;
    const float* hrows = g_h + (size_t)g_offset[e] * (size_t)KDIM; // phase2 A

    int tid = threadIdx.x;

    // --- A load mapping: 2 float4 per thread (BM x BK = 2048 floats) ---
    int acol = (tid & 3) * 4;           // 0,4,8,12
    int arow[2];
    const float* aptr[2];
#pragma unroll
    for (int i = 0; i < 2; i++) {
        int r = (tid >> 2) + i * 64;    // 0..127
        arow[i] = r;
        int m = m0 + r;
        if (m < cnt) {
            if (PHASE1)
                aptr[i] = Aglob + (size_t)g_tok[e][m] * KDIM + acol;
            else
                aptr[i] = hrows + (size_t)m * KDIM + acol;
        } else {
            aptr[i] = nullptr;
        }
    }
    // --- B load mapping: 1 float4 per thread (BK x BN = 1024 floats) ---
    int bkr = tid >> 4;                 // 0..15
    int bnc = (tid & 15) * 4;           // 0..60
    const float* bptr = Bp + (size_t)bkr * N + bnc;

    float4 areg[2], breg;

    auto ldG = [&](int kt) {
#pragma unroll
        for (int i = 0; i < 2; i++)
            areg[i] = aptr[i] ? *(const float4*)(aptr[i] + kt * BK)
                              : make_float4(0.f, 0.f, 0.f, 0.f);
        breg = *(const float4*)(bptr + (size_t)kt * BK * N);
    };
    auto stS = [&](int buf) {
        float* a = As + buf * AS_TILE;
#pragma unroll
        for (int i = 0; i < 2; i++) {
            float4 v = make_float4(wmma::__float_to_tf32(areg[i].x),
                                   wmma::__float_to_tf32(areg[i].y),
                                   wmma::__float_to_tf32(areg[i].z),
                                   wmma::__float_to_tf32(areg[i].w));
            *(float4*)(a + arow[i] * AS_STRIDE + acol) = v;
        }
        float4 w = make_float4(wmma::__float_to_tf32(breg.x),
                               wmma::__float_to_tf32(breg.y),
                               wmma::__float_to_tf32(breg.z),
                               wmma::__float_to_tf32(breg.w));
        *(float4*)(Bs + buf * BS_TILE + bkr * BS_STRIDE + bnc) = w;
    };

    // --- warp tiling: 8 warps, 4(m) x 2(n), each 32x32 ---
    int warp = tid >> 5;
    int wm   = (warp >> 1) * 32;
    int wn   = (warp & 1) * 32;

    wmma::fragment<wmma::accumulator, 16, 16, 8, float> c[2][2];
#pragma unroll
    for (int i = 0; i < 2; i++)
#pragma unroll
        for (int j = 0; j < 2; j++) wmma::fill_fragment(c[i][j], 0.0f);

    auto compute = [&](int buf) {
        const float* a = As + buf * AS_TILE;
        const float* b = Bs + buf * BS_TILE;
#pragma unroll
        for (int kk = 0; kk < BK; kk += 8) {
            wmma::fragment<wmma::matrix_a, 16, 16, 8, wmma::precision::tf32, wmma::row_major> af[2];
            wmma::fragment<wmma::matrix_b, 16, 16, 8, wmma::precision::tf32, wmma::row_major> bf[2];
#pragma unroll
            for (int i = 0; i < 2; i++)
                wmma::load_matrix_sync(af[i], a + (wm + i * 16) * AS_STRIDE + kk, AS_STRIDE);
#pragma unroll
            for (int j = 0; j < 2; j++)
                wmma::load_matrix_sync(bf[j], b + kk * BS_STRIDE + wn + j * 16, BS_STRIDE);
#pragma unroll
            for (int i = 0; i < 2; i++)
#pragma unroll
                for (int j = 0; j < 2; j++)
                    wmma::mma_sync(c[i][j], af[i], bf[j], c[i][j]);
        }
    };

    // --- mainloop: register prefetch + double-buffered smem, 1 sync/iter ---
    constexpr int KT = KDIM / BK;
    ldG(0);
    stS(0);
    __syncthreads();
#pragma unroll 1
    for (int kt = 0; kt < KT; kt++) {
        int cur = kt & 1;
        if (kt + 1 < KT) ldG(kt + 1);
        compute(cur);
        if (kt + 1 < KT) {
            stS((kt + 1) & 1);
            __syncthreads();
        }
    }
    __syncthreads();

    // --- epilogue: stage C in smem, apply bias (+relu / +scaled atomic) ---
#pragma unroll
    for (int i = 0; i < 2; i++)
#pragma unroll
        for (int j = 0; j < 2; j++)
            wmma::store_matrix_sync(sbuf + (wm + i * 16) * C_STRIDE + wn + j * 16,
                                    c[i][j], C_STRIDE, wmma::mem_row_major);
    __syncthreads();

    const float* bias = biasg + (size_t)e * N + n0;
    if (PHASE1) {
        float* hb = g_h + (size_t)g_offset[e] * (size_t)N;
#pragma unroll
        for (int i = 0; i < 8; i++) {                 // 2048 float4 / 256 thr
            int f  = tid + i * 256;
            int r  = f >> 4;
            int cc = (f & 15) * 4;
            int m  = m0 + r;
            if (m < cnt) {
                const float* cs = sbuf + r * C_STRIDE + cc;
                float4 bv = *(const float4*)(bias + cc);
                float4 v;
                v.x = fmaxf(cs[0] + bv.x, 0.f);
                v.y = fmaxf(cs[1] + bv.y, 0.f);
                v.z = fmaxf(cs[2] + bv.z, 0.f);
                v.w = fmaxf(cs[3] + bv.w, 0.f);
                *(float4*)(hb + (size_t)m * N + n0 + cc) = v;
            }
        }
    } else {
#pragma unroll
        for (int i = 0; i < 8; i++) {
            int f  = tid + i * 256;
            int r  = f >> 4;
            int cc = (f & 15) * 4;
            int m  = m0 + r;
            if (m < cnt) {
                const float* cs = sbuf + r * C_STRIDE + cc;
                float w   = g_w[e][m];
                int   tok = g_tok[e][m];
                float* op = outg + (size_t)tok * N + n0 + cc;
                const float* bv = bias + cc;
                // exactly 2 atomic adds per output element; 2-operand fp add
                // is commutative -> bitwise deterministic
                atomicAdd(op + 0, w * (cs[0] + bv[0]));
                atomicAdd(op + 1, w * (cs[1] + bv[1]));
                atomicAdd(op + 2, w * (cs[2] + bv[2]));
                atomicAdd(op + 3, w * (cs[3] + bv[3]));
            }
        }
    }
}

// ---------------------------------------------------------------
extern "C" void kernel_launch(void* const* d_in, const int* in_sizes, int n_in,
                              void* d_out, int out_size) {
    const float* xs = (const float*)d_in[0];
    // d_in[1] = top_k (int32 scalar) -- fixed at 2 for this problem
    const float* Wg = (const float*)d_in[2];
    const float* W1 = (const float*)d_in[3];
    const float* b1 = (const float*)d_in[4];
    const float* W2 = (const float*)d_in[5];
    const float* b2 = (const float*)d_in[6];
    float* out = (float*)d_out;

    cudaMemsetAsync(out, 0, (size_t)T_TOK * IDIM_ * sizeof(float));
    zero_counts_kernel<<<1, 32>>>();
    router_kernel<<<(T_TOK * 32 + 1023) / 1024, 1024>>>(xs, Wg);
    compute_offsets_kernel<<<1, 32>>>();
    moe_gemm<IDIM_, HIDDEN_, true>
        <<<dim3(HIDDEN_ / BN, T_TOK / BM, NEXP), THREADS>>>(xs, W1, b1, nullptr);
    moe_gemm<HIDDEN_, IDIM_, false>
        <<<dim3(IDIM_ / BN, T_TOK / BM, NEXP), THREADS>>>(nullptr, W2, b2, out);
}

// round 7
// speedup vs baseline: 2.8026x; 2.4986x over previous
#include <cuda_runtime.h>
#include <cuda_bf16.h>
#include <mma.h>
#include <cstdint>

using namespace nvcuda;

#define T_TOK   2048
#define IDIM_   1024
#define HIDDEN_ 4096
#define NEXP    8

// Feature gate: tcgen05 PTX is only legal when the device pass targets an
// arch-specific ('a') Blackwell target. compute_103 (no 'a') must compile it out.
#if !defined(__CUDA_ARCH__) || defined(__CUDA_ARCH_FEAT_SM103_ALL) || \
    defined(__CUDA_ARCH_FEAT_SM100_ALL) || defined(__CUDA_ARCH_SPECIFIC__)
#define TC_PATH 1
#else
#define TC_PATH 0
#endif

// ---- device scratch (allocation-free: static device globals) ----
__device__ int   g_count[NEXP];
__device__ int   g_offset[NEXP];
__device__ int   g_tok[NEXP][T_TOK];
__device__ float g_w[NEXP][T_TOK];
__device__ float g_h[(size_t)2 * T_TOK * HIDDEN_];   // compacted hidden rows
__device__ int   g_use_tc;                            // runtime dispatch flag

// ---------------------------------------------------------------
__global__ void probe_kernel() {
    if (threadIdx.x == 0) {
#if TC_PATH && defined(__CUDA_ARCH__)
        g_use_tc = 1;
#else
        g_use_tc = 0;
#endif
    }
    if (threadIdx.x < NEXP) g_count[threadIdx.x] = 0;
}

__global__ void router_kernel(const float* __restrict__ xs,
                              const float* __restrict__ Wg) {
    int gwarp = (blockIdx.x * blockDim.x + threadIdx.x) >> 5;
    int lane  = threadIdx.x & 31;
    if (gwarp >= T_TOK) return;
    const float4* x = (const float4*)(xs + (size_t)gwarp * IDIM_);
    float acc[NEXP];
#pragma unroll
    for (int e = 0; e < NEXP; e++) acc[e] = 0.f;
    for (int k = lane; k < IDIM_ / 4; k += 32) {
        float4 xv = x[k];
#pragma unroll
        for (int e = 0; e < NEXP; e++) {
            const float4 wv = ((const float4*)(Wg + e * IDIM_))[k];
            acc[e] += xv.x * wv.x + xv.y * wv.y + xv.z * wv.z + xv.w * wv.w;
        }
    }
#pragma unroll
    for (int e = 0; e < NEXP; e++)
#pragma unroll
        for (int off = 16; off; off >>= 1)
            acc[e] += __shfl_xor_sync(0xffffffffu, acc[e], off);
    if (lane == 0) {
        int i0 = 0; float v0 = acc[0];
#pragma unroll
        for (int e = 1; e < NEXP; e++) if (acc[e] > v0) { v0 = acc[e]; i0 = e; }
        int i1 = -1; float v1 = -3.4e38f;
#pragma unroll
        for (int e = 0; e < NEXP; e++) if (e != i0 && acc[e] > v1) { v1 = acc[e]; i1 = e; }
        float e1 = expf(v1 - v0);
        float s  = 1.0f + e1;
        int s0 = atomicAdd(&g_count[i0], 1);
        g_tok[i0][s0] = gwarp; g_w[i0][s0] = 1.0f / s;
        int s1 = atomicAdd(&g_count[i1], 1);
        g_tok[i1][s1] = gwarp; g_w[i1][s1] = e1 / s;
    }
}

__global__ void compute_offsets_kernel() {
    if (threadIdx.x == 0) {
        int off = 0;
#pragma unroll
        for (int e = 0; e < NEXP; e++) { g_offset[e] = off; off += g_count[e]; }
    }
}

// ===============================================================
// Path A: wmma tf32 (legacy HMMA) — always available.
// BM=128, BN=128, BK=16, 256 threads, warp tile 32x64.
// ===============================================================
#define WBM 128
#define WBN 128
#define WBK 16
#define WAS_STRIDE 20                 /* 16+4 */
#define WAS_TILE   (WBM * WAS_STRIDE) /* 2560 */
#define WBS_STRIDE 132                /* 128+4 */
#define WBS_TILE   (WBK * WBS_STRIDE) /* 2112 */
#define WC_STRIDE  132
#define WSMEM_BYTES (WBM * WC_STRIDE * 4)  /* 67584 >= (2*WAS+2*WBS)*4=37376 */

template <int KDIM, int N, bool PHASE1>
__global__ __launch_bounds__(256, 2)
void moe_gemm_wmma(const float* __restrict__ Aglob,
                   const float* __restrict__ Bglob,
                   const float* __restrict__ biasg,
                   float* __restrict__ outg) {
    if (g_use_tc) return;
    int e   = blockIdx.z;
    int cnt = g_count[e];
    int m0  = blockIdx.y * WBM;
    if (m0 >= cnt) return;
    int n0  = blockIdx.x * WBN;

    extern __shared__ __align__(16) float sbuf[];
    float* As = sbuf;                   // [2][WAS_TILE]
    float* Bs = sbuf + 2 * WAS_TILE;    // [2][WBS_TILE]

    const float* Bp    = Bglob + (size_t)e * KDIM * N + n0;
    const float* hrows = g_h + (size_t)g_offset[e] * (size_t)KDIM;

    int tid = threadIdx.x;

    // A: 128x16 = 2 float4/thread. col=(tid&3)*4, rows tid>>2 (+64)
    int acol = (tid & 3) * 4;
    int arow[2];
    const float* aptr[2];
#pragma unroll
    for (int i = 0; i < 2; i++) {
        int r = (tid >> 2) + i * 64;
        arow[i] = r;
        int m = m0 + r;
        if (m < cnt)
            aptr[i] = (PHASE1 ? Aglob + (size_t)g_tok[e][m] * KDIM
                              : hrows + (size_t)m * KDIM) + acol;
        else aptr[i] = nullptr;
    }
    // B: 16x128 = 2 float4/thread. row=tid>>5 (+8), col=(tid&31)*4
    int bkr  = tid >> 5;
    int bnc  = (tid & 31) * 4;
    const float* bptr = Bp + (size_t)bkr * N + bnc;

    float4 areg[2], breg[2];
    auto ldG = [&](int kt) {
#pragma unroll
        for (int i = 0; i < 2; i++)
            areg[i] = aptr[i] ? *(const float4*)(aptr[i] + kt * WBK)
                              : make_float4(0.f, 0.f, 0.f, 0.f);
#pragma unroll
        for (int i = 0; i < 2; i++)
            breg[i] = *(const float4*)(bptr + (size_t)(kt * WBK + i * 8) * N);
    };
    auto stS = [&](int buf) {
        float* a = As + buf * WAS_TILE;
        float* b = Bs + buf * WBS_TILE;
#pragma unroll
        for (int i = 0; i < 2; i++) {
            float4 v = make_float4(wmma::__float_to_tf32(areg[i].x),
                                   wmma::__float_to_tf32(areg[i].y),
                                   wmma::__float_to_tf32(areg[i].z),
                                   wmma::__float_to_tf32(areg[i].w));
            *(float4*)(a + arow[i] * WAS_STRIDE + acol) = v;
        }
#pragma unroll
        for (int i = 0; i < 2; i++) {
            float4 v = make_float4(wmma::__float_to_tf32(breg[i].x),
                                   wmma::__float_to_tf32(breg[i].y),
                                   wmma::__float_to_tf32(breg[i].z),
                                   wmma::__float_to_tf32(breg[i].w));
            *(float4*)(b + (bkr + i * 8) * WBS_STRIDE + bnc) = v;
        }
    };

    // 8 warps: 4(m) x 2(n); warp tile 32x64
    int warp = tid >> 5;
    int wm   = (warp >> 1) * 32;
    int wn   = (warp & 1) * 64;

    wmma::fragment<wmma::accumulator, 16, 16, 8, float> c[2][4];
#pragma unroll
    for (int i = 0; i < 2; i++)
#pragma unroll
        for (int j = 0; j < 4; j++) wmma::fill_fragment(c[i][j], 0.0f);

    auto compute = [&](int buf) {
        const float* a = As + buf * WAS_TILE;
        const float* b = Bs + buf * WBS_TILE;
#pragma unroll
        for (int kk = 0; kk < WBK; kk += 8) {
            wmma::fragment<wmma::matrix_a, 16, 16, 8, wmma::precision::tf32, wmma::row_major> af[2];
            wmma::fragment<wmma::matrix_b, 16, 16, 8, wmma::precision::tf32, wmma::row_major> bf[4];
#pragma unroll
            for (int i = 0; i < 2; i++)
                wmma::load_matrix_sync(af[i], a + (wm + i * 16) * WAS_STRIDE + kk, WAS_STRIDE);
#pragma unroll
            for (int j = 0; j < 4; j++)
                wmma::load_matrix_sync(bf[j], b + kk * WBS_STRIDE + wn + j * 16, WBS_STRIDE);
#pragma unroll
            for (int i = 0; i < 2; i++)
#pragma unroll
                for (int j = 0; j < 4; j++)
                    wmma::mma_sync(c[i][j], af[i], bf[j], c[i][j]);
        }
    };

    constexpr int KT = KDIM / WBK;
    ldG(0);
    stS(0);
    __syncthreads();
#pragma unroll 1
    for (int kt = 0; kt < KT; kt++) {
        int cur = kt & 1;
        if (kt + 1 < KT) ldG(kt + 1);
        compute(cur);
        if (kt + 1 < KT) {
            stS((kt + 1) & 1);
            __syncthreads();
        }
    }
    __syncthreads();

    // epilogue: stage C (aliases mainloop smem)
#pragma unroll
    for (int i = 0; i < 2; i++)
#pragma unroll
        for (int j = 0; j < 4; j++)
            wmma::store_matrix_sync(sbuf + (wm + i * 16) * WC_STRIDE + wn + j * 16,
                                    c[i][j], WC_STRIDE, wmma::mem_row_major);
    __syncthreads();

    const float* bias = biasg + (size_t)e * N + n0;
    if (PHASE1) {
        float* hb = g_h + (size_t)g_offset[e] * (size_t)N;
#pragma unroll
        for (int i = 0; i < 16; i++) {                 // 4096 float4 / 256 thr
            int f  = tid + i * 256;
            int r  = f >> 5;
            int cc = (f & 31) * 4;
            int m  = m0 + r;
            if (m < cnt) {
                const float* cs = sbuf + r * WC_STRIDE + cc;
                float4 bv = *(const float4*)(bias + cc);
                float4 v;
                v.x = fmaxf(cs[0] + bv.x, 0.f);
                v.y = fmaxf(cs[1] + bv.y, 0.f);
                v.z = fmaxf(cs[2] + bv.z, 0.f);
                v.w = fmaxf(cs[3] + bv.w, 0.f);
                *(float4*)(hb + (size_t)m * N + n0 + cc) = v;
            }
        }
    } else {
#pragma unroll
        for (int i = 0; i < 16; i++) {
            int f  = tid + i * 256;
            int r  = f >> 5;
            int cc = (f & 31) * 4;
            int m  = m0 + r;
            if (m < cnt) {
                const float* cs = sbuf + r * WC_STRIDE + cc;
                float w   = g_w[e][m];
                int   tok = g_tok[e][m];
                float* op = outg + (size_t)tok * N + n0 + cc;
                const float* bv = bias + cc;
                atomicAdd(op + 0, w * (cs[0] + bv[0]));
                atomicAdd(op + 1, w * (cs[1] + bv[1]));
                atomicAdd(op + 2, w * (cs[2] + bv[2]));
                atomicAdd(op + 3, w * (cs[3] + bv[3]));
            }
        }
    }
}

// ===============================================================
// Path B: tcgen05 SS tf32 — only emitted for arch-specific targets.
// ===============================================================
__device__ __forceinline__ uint32_t smem_to_u32(const void* p) {
    uint32_t a;
    asm("{ .reg .u64 t; cvta.to.shared.u64 t, %1; cvt.u32.u64 %0, t; }" : "=r"(a) : "l"(p));
    return a;
}
__device__ __forceinline__ uint32_t elect_one_pred() {
    uint32_t p;
    asm volatile("{\n\t.reg .pred p;\n\telect.sync _|p, 0xFFFFFFFF;\n\tselp.b32 %0, 1, 0, p;\n\t}" : "=r"(p));
    return p;
}
#define MBARRIER_INIT(addr, cnt) \
    asm volatile("mbarrier.init.shared.b64 [%0], %1;" :: "r"((uint32_t)(addr)), "r"((uint32_t)(cnt)) : "memory")
#define MBARRIER_WAIT_PARITY(mbar, par) do {                                   \
    uint32_t _m = (uint32_t)(mbar); uint32_t _p = (uint32_t)(par);             \
    asm volatile("{\n\t.reg .pred P1;\n\t"                                     \
        "WAIT_LOOP_%=:\n\t"                                                    \
        "mbarrier.try_wait.parity.acquire.cta.shared::cta.b64 P1, [%0], %1, 0x989680;\n\t" \
        "@P1 bra.uni WAIT_DONE_%=;\n\t"                                        \
        "bra.uni WAIT_LOOP_%=;\n\t"                                            \
        "WAIT_DONE_%=:\n\t}" :: "r"(_m), "r"(_p) : "memory");                  \
} while (0)
#define FENCE_ASYNC() asm volatile("fence.proxy.async.shared::cta;" ::: "memory")

static __device__ __forceinline__ uint64_t make_desc_sw128(uint32_t addr) {
    const uint64_t base = (uint64_t(2) << 61) | (uint64_t(1) << 46)
                        | (uint64_t(64) << 32) | (uint64_t(1) << 16);
    return base | ((uint64_t)(addr >> 4) & 0x3FFF);
}
__device__ __forceinline__ uint32_t swz(uint32_t off) { return off ^ ((off >> 3) & 0x70); }
__device__ __forceinline__ float to_tf32(float x) {
    float y; asm("cvt.rna.tf32.f32 %0, %1;" : "=f"(y) : "f"(x)); return y;
}

#define IDESC_TF32 ((1u << 4) | (2u << 7) | (2u << 10) | (16u << 17) | (8u << 24))
#define SOFF_TMEM 0
#define SOFF_MB0  16
#define SOFF_MB1  24
#define SOFF_MBD  32
#define SOFF_A    1024
#define ABUF_SZ   16384
#define SOFF_B    (SOFF_A + 2 * ABUF_SZ)
#define BBUF_SZ   16384
#define TC_SMEM   (SOFF_B + 2 * BBUF_SZ)   /* 66560 */

template <int KDIM, int NFEAT, bool PHASE1>
__global__ __launch_bounds__(256, 2)
void moe_mma_tc(const float* __restrict__ act,
                const float* __restrict__ Wt,
                const float* __restrict__ biasg,
                float* __restrict__ outg) {
#if TC_PATH
    int e   = blockIdx.z;
    int cnt = g_count[e];
    int m0  = blockIdx.y * 128;
    if (m0 >= cnt) return;
    int f0  = blockIdx.x * 128;
    int goff = g_offset[e];

    extern __shared__ __align__(1024) char smem[];
    uint32_t sb  = smem_to_u32(smem);
    int tid = threadIdx.x, wid = tid >> 5, lane = tid & 31;

    if (tid == 0) {
        MBARRIER_INIT(sb + SOFF_MB0, 1);
        MBARRIER_INIT(sb + SOFF_MB1, 1);
        MBARRIER_INIT(sb + SOFF_MBD, 1);
    }
    if (wid == 0)
        asm volatile("tcgen05.alloc.cta_group::1.sync.aligned.shared::cta.b32 [%0], %1;"
            :: "r"(sb + SOFF_TMEM), "r"(128u) : "memory");
    __syncthreads();
    uint32_t tmem;
    asm volatile("ld.shared.b32 %0, [%1];" : "=r"(tmem) : "r"(sb + SOFF_TMEM));
    if (wid == 0)
        asm volatile("tcgen05.relinquish_alloc_permit.cta_group::1.sync.aligned;");

    int kg = tid & 7, hg = tid >> 3;
    const float* aptr = Wt + (size_t)e * KDIM * NFEAT + (size_t)(4 * kg) * NFEAT + f0 + 4 * hg;
    uint32_t aoff[4];
#pragma unroll
    for (int j = 0; j < 4; j++) aoff[j] = swz((4 * hg + j) * 128 + 16 * kg);

    int q = tid & 7, rbase = tid >> 3;
    const float* bptr[4];
    uint32_t boff[4];
#pragma unroll
    for (int i = 0; i < 4; i++) {
        int r = rbase + i * 32;
        int m = m0 + r;
        boff[i] = swz(r * 128 + 16 * q);
        if (m < cnt)
            bptr[i] = PHASE1 ? act + (size_t)g_tok[e][m] * KDIM + 4 * q
                             : g_h + (size_t)(goff + m) * KDIM + 4 * q;
        else bptr[i] = nullptr;
    }

    float4 areg[4], breg[4];
    auto ldG = [&](int kt) {
        const float* ap = aptr + (size_t)(kt * 32) * NFEAT;
#pragma unroll
        for (int i = 0; i < 4; i++) areg[i] = *(const float4*)(ap + (size_t)i * NFEAT);
#pragma unroll
        for (int i = 0; i < 4; i++)
            breg[i] = bptr[i] ? *(const float4*)(bptr[i] + kt * 32)
                              : make_float4(0.f, 0.f, 0.f, 0.f);
    };
    auto stS = [&](int b) {
        uint32_t abo = SOFF_A + b * ABUF_SZ;
        uint32_t bbo = SOFF_B + b * BBUF_SZ;
        float c0[4] = {areg[0].x, areg[0].y, areg[0].z, areg[0].w};
        float c1[4] = {areg[1].x, areg[1].y, areg[1].z, areg[1].w};
        float c2[4] = {areg[2].x, areg[2].y, areg[2].z, areg[2].w};
        float c3[4] = {areg[3].x, areg[3].y, areg[3].z, areg[3].w};
#pragma unroll
        for (int j = 0; j < 4; j++) {
            float4 v = make_float4(to_tf32(c0[j]), to_tf32(c1[j]),
                                   to_tf32(c2[j]), to_tf32(c3[j]));
            *(float4*)(smem + abo + aoff[j]) = v;
        }
#pragma unroll
        for (int i = 0; i < 4; i++) {
            float4 v = make_float4(to_tf32(breg[i].x), to_tf32(breg[i].y),
                                   to_tf32(breg[i].z), to_tf32(breg[i].w));
            *(float4*)(smem + bbo + boff[i]) = v;
        }
    };

    constexpr int KT = KDIM / 32;
    uint64_t adb[2] = { make_desc_sw128(sb + SOFF_A),
                        make_desc_sw128(sb + SOFF_A + ABUF_SZ) };
    uint64_t bdb[2] = { make_desc_sw128(sb + SOFF_B),
                        make_desc_sw128(sb + SOFF_B + BBUF_SZ) };
    int ph[2] = {0, 0};

    ldG(0);
#pragma unroll 1
    for (int kt = 0; kt < KT; kt++) {
        int b = kt & 1;
        if (kt >= 2) { MBARRIER_WAIT_PARITY(sb + (b ? SOFF_MB1 : SOFF_MB0), ph[b]); ph[b] ^= 1; }
        stS(b);
        FENCE_ASYNC();
        __syncthreads();
        if (kt + 1 < KT) ldG(kt + 1);
        if (wid == 0 && elect_one_pred()) {
#pragma unroll
            for (int s = 0; s < 4; s++) {
                uint32_t en = (kt == 0 && s == 0) ? 0u : 1u;
                asm volatile("{\n\t.reg .pred p;\n\tsetp.ne.u32 p, %4, 0;\n\t"
                    "tcgen05.mma.cta_group::1.kind::tf32 [%0], %1, %2, %3, {%5,%5,%5,%5}, p;\n\t}"
                    :: "r"(tmem), "l"(adb[b] + s * 2), "l"(bdb[b] + s * 2),
                       "r"((uint32_t)IDESC_TF32), "r"(en), "r"(0u) : "memory");
            }
            asm volatile("tcgen05.commit.cta_group::1.mbarrier::arrive::one.shared::cluster.b64 [%0];"
                :: "r"(sb + (b ? SOFF_MB1 : SOFF_MB0)) : "memory");
        }
    }
    if (wid == 0 && elect_one_pred())
        asm volatile("tcgen05.commit.cta_group::1.mbarrier::arrive::one.shared::cluster.b64 [%0];"
            :: "r"(sb + SOFF_MBD) : "memory");
    MBARRIER_WAIT_PARITY(sb + SOFF_MBD, 0);
    asm volatile("tcgen05.fence::after_thread_sync;" ::: "memory");

    int sub = wid & 3;
    int h   = f0 + sub * 32 + lane;
    float bias = biasg[(size_t)e * NFEAT + h];
    int c0i = (wid < 4) ? 0 : 2;
#pragma unroll
    for (int c = c0i; c < c0i + 2; c++) {
        uint32_t r[32];
        asm volatile("tcgen05.ld.sync.aligned.32x32b.x32.b32 "
            "{%0,%1,%2,%3,%4,%5,%6,%7,%8,%9,%10,%11,%12,%13,%14,%15,"
            "%16,%17,%18,%19,%20,%21,%22,%23,%24,%25,%26,%27,%28,%29,%30,%31}, [%32];"
            : "=r"(r[0]),"=r"(r[1]),"=r"(r[2]),"=r"(r[3]),"=r"(r[4]),"=r"(r[5]),"=r"(r[6]),"=r"(r[7]),
              "=r"(r[8]),"=r"(r[9]),"=r"(r[10]),"=r"(r[11]),"=r"(r[12]),"=r"(r[13]),"=r"(r[14]),"=r"(r[15]),
              "=r"(r[16]),"=r"(r[17]),"=r"(r[18]),"=r"(r[19]),"=r"(r[20]),"=r"(r[21]),"=r"(r[22]),"=r"(r[23]),
              "=r"(r[24]),"=r"(r[25]),"=r"(r[26]),"=r"(r[27]),"=r"(r[28]),"=r"(r[29]),"=r"(r[30]),"=r"(r[31])
            : "r"(tmem + c * 32));
        asm volatile("tcgen05.wait::ld.sync.aligned;" ::: "memory");
#pragma unroll
        for (int t = 0; t < 32; t++) {
            int m = m0 + c * 32 + t;
            if (m < cnt) {
                float v = __uint_as_float(r[t]) + bias;
                if (PHASE1) {
                    v = fmaxf(v, 0.f);
                    g_h[(size_t)(goff + m) * NFEAT + h] = v;
                } else {
                    atomicAdd(&outg[(size_t)g_tok[e][m] * NFEAT + h], g_w[e][m] * v);
                }
            }
        }
    }
    __syncthreads();
    if (wid == 0)
        asm volatile("tcgen05.dealloc.cta_group::1.sync.aligned.b32 %0, %1;"
            :: "r"(tmem), "r"(128u));
#endif  // TC_PATH
}

// ---------------------------------------------------------------
extern "C" void kernel_launch(void* const* d_in, const int* in_sizes, int n_in,
                              void* d_out, int out_size) {
    const float* xs = (const float*)d_in[0];
    // d_in[1] = top_k (int32 scalar) -- fixed at 2 for this problem
    const float* Wg = (const float*)d_in[2];
    const float* W1 = (const float*)d_in[3];
    const float* b1 = (const float*)d_in[4];
    const float* W2 = (const float*)d_in[5];
    const float* b2 = (const float*)d_in[6];
    float* out = (float*)d_out;

    cudaFuncSetAttribute(moe_gemm_wmma<IDIM_, HIDDEN_, true>,
                         cudaFuncAttributeMaxDynamicSharedMemorySize, WSMEM_BYTES);
    cudaFuncSetAttribute(moe_gemm_wmma<HIDDEN_, IDIM_, false>,
                         cudaFuncAttributeMaxDynamicSharedMemorySize, WSMEM_BYTES);
    cudaFuncSetAttribute(moe_mma_tc<IDIM_, HIDDEN_, true>,
                         cudaFuncAttributeMaxDynamicSharedMemorySize, TC_SMEM);
    cudaFuncSetAttribute(moe_mma_tc<HIDDEN_, IDIM_, false>,
                         cudaFuncAttributeMaxDynamicSharedMemorySize, TC_SMEM);

    cudaMemsetAsync(out, 0, (size_t)T_TOK * IDIM_ * sizeof(float));
    probe_kernel<<<1, 32>>>();
    router_kernel<<<(T_TOK * 32 + 1023) / 1024, 1024>>>(xs, Wg);
    compute_offsets_kernel<<<1, 32>>>();

    // Path A (self-disables when g_use_tc == 1)
    moe_gemm_wmma<IDIM_, HIDDEN_, true>
        <<<dim3(HIDDEN_ / WBN, T_TOK / WBM, NEXP), 256, WSMEM_BYTES>>>(xs, W1, b1, nullptr);
    // Path B (empty body unless arch-specific cubin is loaded)
    moe_mma_tc<IDIM_, HIDDEN_, true>
        <<<dim3(HIDDEN_ / 128, T_TOK / 128, NEXP), 256, TC_SMEM>>>(xs, W1, b1, nullptr);

    moe_gemm_wmma<HIDDEN_, IDIM_, false>
        <<<dim3(IDIM_ / WBN, T_TOK / WBM, NEXP), 256, WSMEM_BYTES>>>(nullptr, W2, b2, out);
    moe_mma_tc<HIDDEN_, IDIM_, false>
        <<<dim3(IDIM_ / 128, T_TOK / 128, NEXP), 256, TC_SMEM>>>(nullptr, W2, b2, out);
}